// round 10
// baseline (speedup 1.0000x reference)
#include <cuda_runtime.h>
#include <cstdint>

#define NUM_NODES 50000
#define INPUT_SIZE 128
#define NUM_REL 16
#define NUM_EDGES 1600000
#define CLAMP_MIN 1e-5f
#define CLAMP_MAX 0.99999f

// Node logit table: T[n][0:16] = x[n].W_src, T[n][16:32] = x[n].W_dst
__device__ float g_table[NUM_NODES * 32];

__device__ __forceinline__ uint32_t f2tf32(float f) {
    uint32_t r;
    asm("cvt.rna.tf32.f32 %0, %1;" : "=r"(r) : "f"(f));
    return r;
}

__device__ __forceinline__ void mma_tf32(float* d, const uint32_t* a, const uint32_t* b) {
    asm volatile(
        "mma.sync.aligned.m16n8k8.row.col.f32.tf32.tf32.f32 "
        "{%0,%1,%2,%3}, {%4,%5,%6,%7}, {%8,%9}, {%0,%1,%2,%3};"
        : "+f"(d[0]), "+f"(d[1]), "+f"(d[2]), "+f"(d[3])
        : "r"(a[0]), "r"(a[1]), "r"(a[2]), "r"(a[3]), "r"(b[0]), "r"(b[1]));
}

// ---------------------------------------------------------------------------
// Kernel A: 50000x128 @ 128x32 GEMM via tf32 tensor cores, 3-term split
// (xh*wh + xh*wl + xl*wh) for fp32-grade accuracy.
// 128 thr/block = 4 warps; warp w -> rows w*32..w*32+31 (2 m16 tiles) x N=32
// (4 n8 tiles). K processed in 4 chunks of 32 (4 k8 steps each).
// ---------------------------------------------------------------------------
__global__ void __launch_bounds__(128) node_logits_kernel(
    const float* __restrict__ x, const float* __restrict__ W)
{
    __shared__ float Xh[128][33], Xl[128][33];   // [node][k-in-chunk], 33.8 KB
    __shared__ float Wh[32][33],  Wl[32][33];    // [k-in-chunk][col],   8.4 KB

    const int tid  = threadIdx.x;
    const int warp = tid >> 5;
    const int lane = tid & 31;
    const int g    = lane >> 2;   // 0..7
    const int tig  = lane & 3;    // 0..3
    const int node0 = blockIdx.x * 128;

    // X staging: thread t owns node0+t's row.
    int node = node0 + tid;
    if (node >= NUM_NODES) node = NUM_NODES - 1;          // dup loads OK
    const float* xrow = x + (size_t)node * INPUT_SIZE;

    // W staging: thread handles 8 combined-cols: k = tid>>2 (+kc*32), r0 = (tid&3)*8.
    const int wk_local = tid >> 2;        // 0..31 (k within chunk)
    const int wr0      = (tid & 3) * 8;   // 0,8,16,24
    // combined col r maps: r<16 -> W[k][r]; r>=16 -> W[k+128][r-16]. r0-block never crosses 16.
    const int wrow_add = (wr0 < 16) ? 0 : INPUT_SIZE;
    const int wcol     = (wr0 < 16) ? wr0 : wr0 - 16;

    float acc[2][4][4];
#pragma unroll
    for (int mt = 0; mt < 2; ++mt)
#pragma unroll
        for (int nt = 0; nt < 4; ++nt)
#pragma unroll
            for (int i = 0; i < 4; ++i) acc[mt][nt][i] = 0.0f;

    // Prefetch chunk 0.
    float4 xv[8];
    float4 wv[2];
#pragma unroll
    for (int it = 0; it < 8; ++it)
        xv[it] = *reinterpret_cast<const float4*>(xrow + it * 4);
    {
        const float* wp = W + (size_t)wk_local * NUM_REL + (size_t)wrow_add * NUM_REL + wcol;
        wv[0] = *reinterpret_cast<const float4*>(wp);
        wv[1] = *reinterpret_cast<const float4*>(wp + 4);
    }

#pragma unroll
    for (int kc = 0; kc < 4; ++kc) {
        __syncthreads();   // previous chunk's reads complete

        // Stage X (split): thread t writes its own row -> conflict-free across lanes.
#pragma unroll
        for (int it = 0; it < 8; ++it) {
            float xf[4] = {xv[it].x, xv[it].y, xv[it].z, xv[it].w};
#pragma unroll
            for (int j = 0; j < 4; ++j) {
                float hf = __uint_as_float(f2tf32(xf[j]));
                float lf = xf[j] - hf;
                Xh[tid][it * 4 + j] = hf;
                Xl[tid][it * 4 + j] = __uint_as_float(f2tf32(lf));
            }
        }
        // Stage W (split).
#pragma unroll
        for (int h = 0; h < 2; ++h) {
            float wf[4] = { (&wv[h].x)[0], (&wv[h].x)[1], (&wv[h].x)[2], (&wv[h].x)[3] };
#pragma unroll
            for (int j = 0; j < 4; ++j) {
                float hf = __uint_as_float(f2tf32(wf[j]));
                float lf = wf[j] - hf;
                Wh[wk_local][wr0 + h * 4 + j] = hf;
                Wl[wk_local][wr0 + h * 4 + j] = __uint_as_float(f2tf32(lf));
            }
        }
        __syncthreads();

        // Prefetch next chunk while tensor cores chew on this one.
        if (kc < 3) {
#pragma unroll
            for (int it = 0; it < 8; ++it)
                xv[it] = *reinterpret_cast<const float4*>(xrow + (kc + 1) * 32 + it * 4);
            const float* wp = W + (size_t)((kc + 1) * 32 + wk_local + wrow_add) * NUM_REL + wcol;
            wv[0] = *reinterpret_cast<const float4*>(wp);
            wv[1] = *reinterpret_cast<const float4*>(wp + 4);
        }

        // Compute: 4 k8 steps.
#pragma unroll
        for (int ks = 0; ks < 4; ++ks) {
            const int k0 = ks * 8;
            uint32_t ah[2][4], al[2][4];
#pragma unroll
            for (int mt = 0; mt < 2; ++mt) {
                const int mb = warp * 32 + mt * 16;
                ah[mt][0] = __float_as_uint(Xh[mb + g][k0 + tig]);
                ah[mt][1] = __float_as_uint(Xh[mb + g + 8][k0 + tig]);
                ah[mt][2] = __float_as_uint(Xh[mb + g][k0 + tig + 4]);
                ah[mt][3] = __float_as_uint(Xh[mb + g + 8][k0 + tig + 4]);
                al[mt][0] = __float_as_uint(Xl[mb + g][k0 + tig]);
                al[mt][1] = __float_as_uint(Xl[mb + g + 8][k0 + tig]);
                al[mt][2] = __float_as_uint(Xl[mb + g][k0 + tig + 4]);
                al[mt][3] = __float_as_uint(Xl[mb + g + 8][k0 + tig + 4]);
            }
            uint32_t bh[4][2], bl[4][2];
#pragma unroll
            for (int nt = 0; nt < 4; ++nt) {
                bh[nt][0] = __float_as_uint(Wh[k0 + tig][nt * 8 + g]);
                bh[nt][1] = __float_as_uint(Wh[k0 + tig + 4][nt * 8 + g]);
                bl[nt][0] = __float_as_uint(Wl[k0 + tig][nt * 8 + g]);
                bl[nt][1] = __float_as_uint(Wl[k0 + tig + 4][nt * 8 + g]);
            }
#pragma unroll
            for (int mt = 0; mt < 2; ++mt)
#pragma unroll
                for (int nt = 0; nt < 4; ++nt) {
                    mma_tf32(acc[mt][nt], ah[mt], bh[nt]);
                    mma_tf32(acc[mt][nt], ah[mt], bl[nt]);
                    mma_tf32(acc[mt][nt], al[mt], bh[nt]);
                }
        }
    }

    // Epilogue: c0/c1 -> row mb+g, cols nt*8+tig*2(+1); c2/c3 -> row mb+g+8.
#pragma unroll
    for (int mt = 0; mt < 2; ++mt) {
        const int mb = warp * 32 + mt * 16;
        const int r0 = node0 + mb + g;
        const int r1 = r0 + 8;
#pragma unroll
        for (int nt = 0; nt < 4; ++nt) {
            const int col = nt * 8 + tig * 2;
            if (r0 < NUM_NODES)
                *reinterpret_cast<float2*>(&g_table[(size_t)r0 * 32 + col]) =
                    make_float2(acc[mt][nt][0], acc[mt][nt][1]);
            if (r1 < NUM_NODES)
                *reinterpret_cast<float2*>(&g_table[(size_t)r1 * 32 + col]) =
                    make_float2(acc[mt][nt][2], acc[mt][nt][3]);
        }
    }
}

// ---------------------------------------------------------------------------
// FMA/ALU-only clamped sigmoid (no MUFU; proven rel_err ~3e-7).
// ---------------------------------------------------------------------------
__device__ __forceinline__ float sigmoid_clamped(float v)
{
    v = fminf(fmaxf(v, -15.0f), 15.0f);
    float y = v * -1.4426950408889634f;
    float z = y + 12582912.0f;
    int   n = __float_as_int(z) - 0x4B400000;
    float f = y - (z - 12582912.0f);
    float p = 0.0013333558f;
    p = fmaf(p, f, 0.0096181291f);
    p = fmaf(p, f, 0.0555041086f);
    p = fmaf(p, f, 0.2402265069f);
    p = fmaf(p, f, 0.6931471806f);
    p = fmaf(p, f, 1.0f);
    float e = p * __int_as_float((n + 127) << 23);
    float d = 1.0f + e;
    float r = __int_as_float(0x7EF311C3 - __float_as_int(d));
    r = r * (2.0f - d * r);
    r = r * (2.0f - d * r);
    r = r * (2.0f - d * r);
    return fminf(fmaxf(r, CLAMP_MIN), CLAMP_MAX);
}

// ---------------------------------------------------------------------------
// Kernel B: 1 edge/thread (measured-best; at the divergent-gather HW floor).
// ---------------------------------------------------------------------------
__global__ void __launch_bounds__(256) edge_kernel(
    const int* __restrict__ ei,
    const int* __restrict__ et,
    float* __restrict__ out)
{
    const int e = blockIdx.x * 256 + threadIdx.x;
    if (e < NUM_EDGES) {
        int s = ei[e];
        int d = ei[NUM_EDGES + e];
        int t = et[e];
        float a = __ldg(&g_table[s * 32 + t]);
        float b = __ldg(&g_table[d * 32 + 16 + t]);
        out[e] = sigmoid_clamped(a + b);
    }
}

extern "C" void kernel_launch(void* const* d_in, const int* in_sizes, int n_in,
                              void* d_out, int out_size)
{
    const float* x  = (const float*)d_in[0];
    const float* W  = (const float*)d_in[1];
    const int*   ei = (const int*)d_in[2];
    const int*   et = (const int*)d_in[3];
    float* out = (float*)d_out;

    const int node_blocks = (NUM_NODES + 127) / 128;       // 391
    node_logits_kernel<<<node_blocks, 128>>>(x, W);

    const int edge_blocks = (NUM_EDGES + 255) / 256;       // 6250
    edge_kernel<<<edge_blocks, 256>>>(ei, et, out);
}

// round 12
// speedup vs baseline: 1.3792x; 1.3792x over previous
#include <cuda_runtime.h>
#include <cuda_bf16.h>
#include <cstdint>

#define NUM_NODES 50000
#define INPUT_SIZE 128
#define NUM_REL 16
#define NUM_EDGES 1600000
#define CLAMP_MIN 1e-5f
#define CLAMP_MAX 0.99999f

__device__ float g_table[NUM_NODES * 32];

// ---------------- helpers ----------------
__device__ __forceinline__ uint32_t smem_u32(const void* p) {
    uint32_t a;
    asm("{ .reg .u64 t; cvta.to.shared.u64 t, %1; cvt.u32.u64 %0, t; }" : "=r"(a) : "l"(p));
    return a;
}
__device__ __forceinline__ uint32_t pack_bf16x2(float a, float b) {
    __nv_bfloat162 h = __floats2bfloat162_rn(a, b);   // .x=a (low), .y=b (high)
    return *reinterpret_cast<uint32_t*>(&h);
}
__device__ __forceinline__ void split_bf16(float f, float& hi_f, float& lo_f) {
    __nv_bfloat16 h = __float2bfloat16_rn(f);
    hi_f = __bfloat162float(h);
    lo_f = f - hi_f;
}
__device__ __forceinline__ void ldm_x4(uint32_t addr, uint32_t* r) {
    asm volatile("ldmatrix.sync.aligned.m8n8.x4.shared.b16 {%0,%1,%2,%3}, [%4];"
                 : "=r"(r[0]), "=r"(r[1]), "=r"(r[2]), "=r"(r[3]) : "r"(addr));
}
__device__ __forceinline__ void mma_bf16(float* c, const uint32_t* a, const uint32_t* b) {
    asm volatile("mma.sync.aligned.m16n8k16.row.col.f32.bf16.bf16.f32 "
                 "{%0,%1,%2,%3}, {%4,%5,%6,%7}, {%8,%9}, {%0,%1,%2,%3};"
                 : "+f"(c[0]), "+f"(c[1]), "+f"(c[2]), "+f"(c[3])
                 : "r"(a[0]), "r"(a[1]), "r"(a[2]), "r"(a[3]), "r"(b[0]), "r"(b[1]));
}

// smem: bf16 tiles, 128B row pitch (64 bf16), XOR swizzle on 16B units.
#define XH_OFF 0
#define XL_OFF 16384
#define WH_OFF 32768
#define WL_OFF 36864
#define SM_TOT 40960
#define SADDR(off, row, unit) ((off) + (row) * 128 + ((((unit)) ^ ((row) & 7)) << 4))

// ---------------------------------------------------------------------------
// Kernel A: 50000x128 @ 128x32 GEMM via mma.sync bf16 m16n8k16, 3-term split.
// 128 thr (4 warps); warp w -> rows w*32..+31 (2 m16) x 32 cols (4 n8).
// K in 2 chunks of 64; per chunk 4 k16-steps.
// ---------------------------------------------------------------------------
__global__ void __launch_bounds__(128) node_logits_kernel(
    const float* __restrict__ x, const float* __restrict__ W)
{
    __shared__ __align__(1024) unsigned char sm[SM_TOT];
    const uint32_t sb = smem_u32(sm);

    const int tid  = threadIdx.x;
    const int warp = tid >> 5;
    const int lane = tid & 31;
    const int g    = lane >> 2;
    const int tig  = lane & 3;
    const int tl   = lane >> 3;          // ldmatrix tile id 0..3
    const int wi   = lane & 7;           // ldmatrix row-within-tile
    const int node0 = blockIdx.x * 128;

    // A staging: thread owns node row tid.
    int node = node0 + tid;
    if (node >= NUM_NODES) node = NUM_NODES - 1;          // dup loads OK
    const float* xrow = x + (size_t)node * INPUT_SIZE;

    // W staging: n = tid&31, k-quarter = tid>>5 (16 k-values).
    const int wn = tid & 31;
    const int wkq = tid >> 5;
    const float* wbase = (wn < NUM_REL) ? (W + wn) : (W + INPUT_SIZE * NUM_REL + (wn - NUM_REL));

    // ldmatrix lane-address row components (constant per thread).
    const int rowA0 = warp * 32 + wi + ((tl & 1) << 3);        // mt adds 16
    const int rowB0 = wi + ((tl >= 2) ? 8 : 0);                // ngrp adds 16
    const int unitA_add = tl >> 1;                             // + ks*2
    const int unitB_add = tl & 1;

    float acc[2][4][4];
#pragma unroll
    for (int mt = 0; mt < 2; ++mt)
#pragma unroll
        for (int nt = 0; nt < 4; ++nt)
#pragma unroll
            for (int i = 0; i < 4; ++i) acc[mt][nt][i] = 0.0f;

    for (int kc = 0; kc < 2; ++kc) {
        __syncthreads();   // previous chunk reads complete

        // ---- stage X chunk: 64 floats of own row -> bf16 hi/lo, swizzled ----
#pragma unroll
        for (int u = 0; u < 8; ++u) {
            float4 va = *reinterpret_cast<const float4*>(xrow + kc * 64 + u * 8);
            float4 vb = *reinterpret_cast<const float4*>(xrow + kc * 64 + u * 8 + 4);
            float f[8] = {va.x, va.y, va.z, va.w, vb.x, vb.y, vb.z, vb.w};
            float h[8], l[8];
#pragma unroll
            for (int j = 0; j < 8; ++j) split_bf16(f[j], h[j], l[j]);
            uint4 hh = make_uint4(pack_bf16x2(h[0], h[1]), pack_bf16x2(h[2], h[3]),
                                  pack_bf16x2(h[4], h[5]), pack_bf16x2(h[6], h[7]));
            uint4 ll = make_uint4(pack_bf16x2(l[0], l[1]), pack_bf16x2(l[2], l[3]),
                                  pack_bf16x2(l[4], l[5]), pack_bf16x2(l[6], l[7]));
            *reinterpret_cast<uint4*>(sm + SADDR(XH_OFF, tid, u)) = hh;
            *reinterpret_cast<uint4*>(sm + SADDR(XL_OFF, tid, u)) = ll;
        }

        // ---- stage W chunk: Wsmem[n][k] = Wcomb[kc*64+k][n], 16 k per thread ----
        {
            float h[16], l[16];
#pragma unroll
            for (int j = 0; j < 16; ++j) {
                int gk = kc * 64 + wkq * 16 + j;
                float wf = wbase[(size_t)gk * NUM_REL];
                split_bf16(wf, h[j], l[j]);
            }
#pragma unroll
            for (int b = 0; b < 2; ++b) {
                int u = wkq * 2 + b;
                uint4 hh = make_uint4(pack_bf16x2(h[b*8+0], h[b*8+1]), pack_bf16x2(h[b*8+2], h[b*8+3]),
                                      pack_bf16x2(h[b*8+4], h[b*8+5]), pack_bf16x2(h[b*8+6], h[b*8+7]));
                uint4 ll = make_uint4(pack_bf16x2(l[b*8+0], l[b*8+1]), pack_bf16x2(l[b*8+2], l[b*8+3]),
                                      pack_bf16x2(l[b*8+4], l[b*8+5]), pack_bf16x2(l[b*8+6], l[b*8+7]));
                *reinterpret_cast<uint4*>(sm + SADDR(WH_OFF, wn, u)) = hh;
                *reinterpret_cast<uint4*>(sm + SADDR(WL_OFF, wn, u)) = ll;
            }
        }
        __syncthreads();

        // ---- compute: 4 k16 steps ----
#pragma unroll
        for (int ks = 0; ks < 4; ++ks) {
            const int uA = ks * 2 + unitA_add;
            const int uB = ks * 2 + unitB_add;
            uint32_t ah[2][4], al[2][4];
#pragma unroll
            for (int mt = 0; mt < 2; ++mt) {
                int r = rowA0 + mt * 16;
                ldm_x4(sb + SADDR(XH_OFF, r, uA), ah[mt]);
                ldm_x4(sb + SADDR(XL_OFF, r, uA), al[mt]);
            }
            uint32_t bh[4][2], bl[4][2];
#pragma unroll
            for (int nh = 0; nh < 2; ++nh) {    // n-groups {0,8} and {16,24}
                int r = rowB0 + nh * 16;
                uint32_t t0[4], t1[4];
                ldm_x4(sb + SADDR(WH_OFF, r, uB), t0);
                ldm_x4(sb + SADDR(WL_OFF, r, uB), t1);
                bh[nh*2+0][0] = t0[0]; bh[nh*2+0][1] = t0[1];
                bh[nh*2+1][0] = t0[2]; bh[nh*2+1][1] = t0[3];
                bl[nh*2+0][0] = t1[0]; bl[nh*2+0][1] = t1[1];
                bl[nh*2+1][0] = t1[2]; bl[nh*2+1][1] = t1[3];
            }
#pragma unroll
            for (int mt = 0; mt < 2; ++mt)
#pragma unroll
                for (int nt = 0; nt < 4; ++nt) {
                    mma_bf16(acc[mt][nt], ah[mt], bh[nt]);
                    mma_bf16(acc[mt][nt], ah[mt], bl[nt]);
                    mma_bf16(acc[mt][nt], al[mt], bh[nt]);
                }
        }
    }

    // ---- epilogue: c0,c1 -> row m0+g; c2,c3 -> row m0+8+g; cols nt*8+2*tig ----
#pragma unroll
    for (int mt = 0; mt < 2; ++mt) {
        const int m0 = warp * 32 + mt * 16;
        const int r0 = node0 + m0 + g;
        const int r1 = r0 + 8;
#pragma unroll
        for (int nt = 0; nt < 4; ++nt) {
            const int col = nt * 8 + tig * 2;
            if (r0 < NUM_NODES)
                *reinterpret_cast<float2*>(&g_table[(size_t)r0 * 32 + col]) =
                    make_float2(acc[mt][nt][0], acc[mt][nt][1]);
            if (r1 < NUM_NODES)
                *reinterpret_cast<float2*>(&g_table[(size_t)r1 * 32 + col]) =
                    make_float2(acc[mt][nt][2], acc[mt][nt][3]);
        }
    }
}

// ---------------------------------------------------------------------------
// FMA/ALU-only clamped sigmoid (no MUFU; proven rel_err ~3e-7).
// ---------------------------------------------------------------------------
__device__ __forceinline__ float sigmoid_clamped(float v)
{
    v = fminf(fmaxf(v, -15.0f), 15.0f);
    float y = v * -1.4426950408889634f;
    float z = y + 12582912.0f;
    int   n = __float_as_int(z) - 0x4B400000;
    float f = y - (z - 12582912.0f);
    float p = 0.0013333558f;
    p = fmaf(p, f, 0.0096181291f);
    p = fmaf(p, f, 0.0555041086f);
    p = fmaf(p, f, 0.2402265069f);
    p = fmaf(p, f, 0.6931471806f);
    p = fmaf(p, f, 1.0f);
    float e = p * __int_as_float((n + 127) << 23);
    float dd = 1.0f + e;
    float r = __int_as_float(0x7EF311C3 - __float_as_int(dd));
    r = r * (2.0f - dd * r);
    r = r * (2.0f - dd * r);
    r = r * (2.0f - dd * r);
    return fminf(fmaxf(r, CLAMP_MIN), CLAMP_MAX);
}

// ---------------------------------------------------------------------------
// Kernel B: 1 edge/thread (measured-best; at the divergent-gather HW floor).
// ---------------------------------------------------------------------------
__global__ void __launch_bounds__(256) edge_kernel(
    const int* __restrict__ ei,
    const int* __restrict__ et,
    float* __restrict__ out)
{
    const int e = blockIdx.x * 256 + threadIdx.x;
    if (e < NUM_EDGES) {
        int s = ei[e];
        int d = ei[NUM_EDGES + e];
        int t = et[e];
        float a = __ldg(&g_table[s * 32 + t]);
        float b = __ldg(&g_table[d * 32 + 16 + t]);
        out[e] = sigmoid_clamped(a + b);
    }
}

extern "C" void kernel_launch(void* const* d_in, const int* in_sizes, int n_in,
                              void* d_out, int out_size)
{
    const float* x  = (const float*)d_in[0];
    const float* W  = (const float*)d_in[1];
    const int*   ei = (const int*)d_in[2];
    const int*   et = (const int*)d_in[3];
    float* out = (float*)d_out;

    const int node_blocks = (NUM_NODES + 127) / 128;       // 391
    node_logits_kernel<<<node_blocks, 128>>>(x, W);

    const int edge_blocks = (NUM_EDGES + 255) / 256;       // 6250
    edge_kernel<<<edge_blocks, 256>>>(ei, et, out);
}